// round 7
// baseline (speedup 1.0000x reference)
#include <cuda_runtime.h>
#include <cstdint>

#define C_IN    64
#define C_OUT   32
#define M_TILE  128
#define THREADS 128
#define GRID    444
#define A_STRIDE_F  68                 // floats per A row (64 + 4 pad, conflict-free)
#define A_ROW_BYTES (A_STRIDE_F * 4)   // 272
#define WARP_A_BYTES (32 * A_ROW_BYTES)  // 8704, per-warp A slice (reused as scratch)
#define SCR_STRIDE 36                  // scratch floats/row: LDS.128 phase conflict-free

// dynamic smem layout (byte offsets, all 16B aligned)
#define OFF_IN(s)   ((s) * 1024)            // 2 x 128 x int64 (or int32)
#define OFF_OUT(s)  (2048 + (s) * 1024)
#define OFF_MBAR    4096                    // 2 mbarriers
#define OFF_A(s)    (4352 + (s) * 34816)    // 2 x 128 x 272B
#define SMEM_TOTAL  (4352 + 2 * 34816)      // 73984

// Runtime-detected index width (reference's int64 maps may have been silently
// downcast to int32 by JAX when x64 is disabled).
__device__ int g_idx_is64;
__global__ void detect_idx_kernel(const long long* __restrict__ im) {
    int is64 = 1;
#pragma unroll
    for (int t = 0; t < 16; ++t) {
        long long v = im[t];
        if (v < 0 || v >= (1ll << 31)) is64 = 0;
    }
    g_idx_is64 = is64;
}

static __device__ __forceinline__ uint32_t smem_u32(const void* p) {
    uint32_t a;
    asm("{ .reg .u64 t; cvta.to.shared.u64 t, %1; cvt.u32.u64 %0, t; }" : "=r"(a) : "l"(p));
    return a;
}
static __device__ __forceinline__ uint32_t cvt_tf32(float f) {
    uint32_t r;
    asm("cvt.rna.tf32.f32 %0, %1;" : "=r"(r) : "f"(f));
    return r;
}
static __device__ __forceinline__ void mma_tf32(
    float& c0, float& c1, float& c2, float& c3,
    uint32_t a0, uint32_t a1, uint32_t a2, uint32_t a3,
    uint32_t b0, uint32_t b1)
{
    asm volatile(
        "mma.sync.aligned.m16n8k8.row.col.f32.tf32.tf32.f32 "
        "{%0,%1,%2,%3}, {%4,%5,%6,%7}, {%8,%9}, {%0,%1,%2,%3};"
        : "+f"(c0), "+f"(c1), "+f"(c2), "+f"(c3)
        : "r"(a0), "r"(a1), "r"(a2), "r"(a3), "r"(b0), "r"(b1));
}
static __device__ __forceinline__ void red_v4(const char* p, float4 v) {
    asm volatile("red.global.add.v4.f32 [%0], {%1, %2, %3, %4};"
                 :: "l"(p), "f"(v.x), "f"(v.y), "f"(v.z), "f"(v.w) : "memory");
}
static __device__ __forceinline__ void mbar_init(uint32_t a, uint32_t n) {
    asm volatile("mbarrier.init.shared.b64 [%0], %1;" :: "r"(a), "r"(n) : "memory");
}
static __device__ __forceinline__ void expect_tx(uint32_t a, uint32_t bytes) {
    asm volatile("mbarrier.arrive.expect_tx.shared.b64 _, [%0], %1;"
                 :: "r"(a), "r"(bytes) : "memory");
}
static __device__ __forceinline__ void mbar_wait(uint32_t a, uint32_t ph) {
    asm volatile("{\n\t.reg .pred P1;\n\t"
        "WL_%=:\n\t"
        "mbarrier.try_wait.parity.acquire.cta.shared::cta.b64 P1, [%0], %1, 0x989680;\n\t"
        "@P1 bra.uni WD_%=;\n\t"
        "bra.uni WL_%=;\n\t"
        "WD_%=:\n\t}" :: "r"(a), "r"(ph) : "memory");
}
static __device__ __forceinline__ void bulk_g2s(uint32_t dst, const void* src,
                                                uint32_t bytes, uint32_t mbar) {
    asm volatile(
        "cp.async.bulk.shared::cta.global.mbarrier::complete_tx::bytes [%0], [%1], %2, [%3];"
        :: "r"(dst), "l"(src), "r"(bytes), "r"(mbar) : "memory");
}
#define FENCE_ASYNC() asm volatile("fence.proxy.async.shared::cta;" ::: "memory")

__global__ void __launch_bounds__(THREADS, 3)
spconv_mma(const float* __restrict__ feats, const float* __restrict__ weight,
           const void* __restrict__ in_map, const void* __restrict__ out_map,
           float* __restrict__ out, int M, int tilesPerK, int nTiles, int chunk)
{
    extern __shared__ __align__(16) char smem[];
    const uint32_t sb = smem_u32(smem);

    const int t0 = blockIdx.x * chunk;
    if (t0 >= nTiles) return;
    const int tEnd = min(t0 + chunk, nTiles);

    const int tid  = threadIdx.x;
    const int wid  = tid >> 5;
    const int lane = tid & 31;
    const int grp  = lane >> 2;
    const int tig  = lane & 3;
    const int wbase = wid * 32;
    const int is64  = g_idx_is64;
    const int idxsz = is64 ? 8 : 4;
    char* const outb = (char*)out;

    if (tid == 0) { mbar_init(sb + OFF_MBAR, 1); mbar_init(sb + OFF_MBAR + 8, 1); }
    __syncthreads();

#define MBAR(s) (sb + OFF_MBAR + 8u * (uint32_t)(s))
#define ROWS_OF(t)   min(M_TILE, M - ((t) % tilesPerK) * M_TILE)
#define MAP_OFF(t)   ((long long)((t) / tilesPerK) * M + ((t) % tilesPerK) * M_TILE)

    int ph[2] = {0, 0};
    const int cur0 = t0 & 1, nxt0 = cur0 ^ 1;
    const int rows0 = ROWS_OF(t0);

    // ---- prologue stage A: fetch in-idx(t0) ----
    if (tid == 0) {
        expect_tx(MBAR(cur0), (uint32_t)(rows0 * idxsz));
        bulk_g2s(sb + OFF_IN(cur0), (const char*)in_map + MAP_OFF(t0) * idxsz,
                 rows0 * idxsz, MBAR(cur0));
    }
    mbar_wait(MBAR(cur0), 0); ph[cur0] = 1;

    // ---- prologue stage B: gather A(t0), out-idx(t0), in-idx(t0+1) ----
    {
        int rows1b = (t0 + 1 < tEnd) ? ROWS_OF(t0 + 1) : 0;
        uint32_t bytes = (uint32_t)(rows0 * 256 + rows0 * idxsz + rows1b * idxsz);
        if (tid == 0) expect_tx(MBAR(nxt0), bytes);
        if (tid < rows0) {
            long long ii = is64 ? ((const long long*)(smem + OFF_IN(cur0)))[tid]
                                : (long long)((const int*)(smem + OFF_IN(cur0)))[tid];
            bulk_g2s(sb + OFF_A(cur0) + tid * A_ROW_BYTES, feats + ii * C_IN, 256, MBAR(nxt0));
        }
        if (tid == 0)
            bulk_g2s(sb + OFF_OUT(cur0), (const char*)out_map + MAP_OFF(t0) * idxsz,
                     rows0 * idxsz, MBAR(nxt0));
        if (tid == 1 && rows1b)
            bulk_g2s(sb + OFF_IN(nxt0), (const char*)in_map + MAP_OFF(t0 + 1) * idxsz,
                     rows1b * idxsz, MBAR(nxt0));
    }

    uint32_t B[8][4][2];
    int k_cur = -1;

    for (int t = t0; t < tEnd; ++t) {
        const int cur = t & 1, nxt = cur ^ 1;

        // wait for everything issued last iteration (A[cur], idx for t+1, out-idx t)
        mbar_wait(MBAR(nxt), ph[nxt]); ph[nxt] ^= 1;
        __syncthreads();

        const int k    = t / tilesPerK;
        const int rows = ROWS_OF(t);

        if (k != k_cur) {   // <=2x per CTA (contiguous chunks)
            k_cur = k;
            const float* Wk = weight + (size_t)k * C_IN * C_OUT;
#pragma unroll
            for (int kt = 0; kt < 8; ++kt)
#pragma unroll
                for (int nt = 0; nt < 4; ++nt) {
                    B[kt][nt][0] = cvt_tf32(Wk[(8 * kt + tig)     * C_OUT + 8 * nt + grp]);
                    B[kt][nt][1] = cvt_tf32(Wk[(8 * kt + tig + 4) * C_OUT + 8 * nt + grp]);
                }
        }

        // ---- issue next tile's async fetches (hidden behind MMA+scatter below) ----
        FENCE_ASYNC();
        const int rows1 = (t + 1 < tEnd) ? ROWS_OF(t + 1) : 0;
        const int rows2 = (t + 2 < tEnd) ? ROWS_OF(t + 2) : 0;
        uint32_t bytes = (uint32_t)(rows1 * (256 + idxsz) + rows2 * idxsz);
        if (bytes && tid == 0) expect_tx(MBAR(cur), bytes);
        if (rows1) {
            if (tid < rows1) {
                long long ii = is64 ? ((const long long*)(smem + OFF_IN(nxt)))[tid]
                                    : (long long)((const int*)(smem + OFF_IN(nxt)))[tid];
                bulk_g2s(sb + OFF_A(nxt) + tid * A_ROW_BYTES, feats + ii * C_IN, 256, MBAR(cur));
            }
            if (tid == 0)
                bulk_g2s(sb + OFF_OUT(nxt), (const char*)out_map + MAP_OFF(t + 1) * idxsz,
                         rows1 * idxsz, MBAR(cur));
        }
        if (rows2 && tid == 1)
            bulk_g2s(sb + OFF_IN(cur), (const char*)in_map + MAP_OFF(t + 2) * idxsz,
                     rows2 * idxsz, MBAR(cur));

        // ---- MMA: 32 rows x 32 cols x 64 k per warp ----
        float acc[2][4][4];
#pragma unroll
        for (int mt = 0; mt < 2; ++mt)
#pragma unroll
            for (int nt = 0; nt < 4; ++nt)
#pragma unroll
                for (int i = 0; i < 4; ++i) acc[mt][nt][i] = 0.f;

        const float* A = (const float*)(smem + OFF_A(cur));
#pragma unroll
        for (int kt = 0; kt < 8; ++kt) {
#pragma unroll
            for (int mt = 0; mt < 2; ++mt) {
                const float* Ar = &A[(wbase + mt * 16 + grp) * A_STRIDE_F + kt * 8 + tig];
                uint32_t a0 = __float_as_uint(Ar[0]);
                uint32_t a1 = __float_as_uint(Ar[8 * A_STRIDE_F]);
                uint32_t a2 = __float_as_uint(Ar[4]);
                uint32_t a3 = __float_as_uint(Ar[8 * A_STRIDE_F + 4]);
#pragma unroll
                for (int nt = 0; nt < 4; ++nt)
                    mma_tf32(acc[mt][nt][0], acc[mt][nt][1], acc[mt][nt][2], acc[mt][nt][3],
                             a0, a1, a2, a3, B[kt][nt][0], B[kt][nt][1]);
            }
        }

        // ---- epilogue: warp-private transpose in (now free) A[cur] slice, then v4 reductions ----
        {
            float* scr = (float*)(smem + OFF_A(cur) + wid * WARP_A_BYTES);
#pragma unroll
            for (int mt = 0; mt < 2; ++mt)
#pragma unroll
                for (int nt = 0; nt < 4; ++nt) {
                    int c = 8 * nt + 2 * tig;
                    *(float2*)&scr[(16 * mt + grp)     * SCR_STRIDE + c] =
                        make_float2(acc[mt][nt][0], acc[mt][nt][1]);
                    *(float2*)&scr[(16 * mt + grp + 8) * SCR_STRIDE + c] =
                        make_float2(acc[mt][nt][2], acc[mt][nt][3]);
                }
            __syncwarp();

            const char* osm = smem + OFF_OUT(cur);
            const int rsub = lane >> 3;          // 0..3
            const int c4   = (lane & 7) * 4;     // 0,4,..,28
#pragma unroll
            for (int b = 0; b < 8; ++b) {
                int r = 4 * b + rsub;            // row within warp's 32
                int rg = wbase + r;
                if (rg < rows) {
                    uint32_t oi = is64 ? (uint32_t)((const long long*)osm)[rg]
                                       : (uint32_t)((const int*)osm)[rg];
                    float4 v = *(const float4*)&scr[r * SCR_STRIDE + c4];
                    red_v4(outb + (oi * 128u + (uint32_t)(c4 * 4)), v);
                }
            }
        }
    }
#undef MBAR
#undef ROWS_OF
#undef MAP_OFF
}

extern "C" void kernel_launch(void* const* d_in, const int* in_sizes, int n_in,
                              void* d_out, int out_size) {
    const float* feats  = (const float*)d_in[0];
    const float* weight = (const float*)d_in[1];
    const void*  in_map  = d_in[2];
    const void*  out_map = d_in[3];

    int K = in_sizes[1] / (C_IN * C_OUT);           // 27
    int M = in_sizes[2] / K;                        // 100000
    int tilesPerK = (M + M_TILE - 1) / M_TILE;      // 782
    int nTiles = K * tilesPerK;                     // 21114
    int chunk = (nTiles + GRID - 1) / GRID;         // 48

    static int attr_done = 0;
    if (!attr_done) {
        cudaFuncSetAttribute(spconv_mma,
                             cudaFuncAttributeMaxDynamicSharedMemorySize, SMEM_TOTAL);
        attr_done = 1;
    }

    cudaMemsetAsync(d_out, 0, (size_t)out_size * sizeof(float));
    detect_idx_kernel<<<1, 1>>>((const long long*)in_map);
    spconv_mma<<<GRID, THREADS, SMEM_TOTAL>>>(feats, weight, in_map, out_map,
                                              (float*)d_out, M, tilesPerK, nTiles, chunk);
}

// round 8
// speedup vs baseline: 1.0269x; 1.0269x over previous
#include <cuda_runtime.h>
#include <cstdint>

#define C_IN    64
#define C_OUT   32
#define M_TILE  128
#define THREADS 256
#define GRID    444
#define A_STRIDE_F  68                 // floats per A row (64 + 4 pad, conflict-free)
#define A_ROW_BYTES (A_STRIDE_F * 4)   // 272

// dynamic smem layout (byte offsets, all 16B aligned)
#define OFF_IN(s)   ((s) * 1024)            // 2 x 128 x int64 (or int32)
#define OFF_OUT(s)  (2048 + (s) * 1024)
#define OFF_MBAR    4096                    // 2 mbarriers
#define OFF_A(s)    (4352 + (s) * 34816)    // 2 x 128 x 272B
#define SMEM_TOTAL  (4352 + 2 * 34816)      // 73984

// Runtime-detected index width (reference's int64 maps may have been silently
// downcast to int32 by JAX when x64 is disabled).
__device__ int g_idx_is64;
__global__ void detect_idx_kernel(const long long* __restrict__ im) {
    int is64 = 1;
#pragma unroll
    for (int t = 0; t < 16; ++t) {
        long long v = im[t];
        if (v < 0 || v >= (1ll << 31)) is64 = 0;
    }
    g_idx_is64 = is64;
}

static __device__ __forceinline__ uint32_t smem_u32(const void* p) {
    uint32_t a;
    asm("{ .reg .u64 t; cvta.to.shared.u64 t, %1; cvt.u32.u64 %0, t; }" : "=r"(a) : "l"(p));
    return a;
}
static __device__ __forceinline__ uint32_t cvt_tf32(float f) {
    uint32_t r;
    asm("cvt.rna.tf32.f32 %0, %1;" : "=r"(r) : "f"(f));
    return r;
}
static __device__ __forceinline__ void mma_tf32(
    float& c0, float& c1, float& c2, float& c3,
    uint32_t a0, uint32_t a1, uint32_t a2, uint32_t a3,
    uint32_t b0, uint32_t b1)
{
    asm volatile(
        "mma.sync.aligned.m16n8k8.row.col.f32.tf32.tf32.f32 "
        "{%0,%1,%2,%3}, {%4,%5,%6,%7}, {%8,%9}, {%0,%1,%2,%3};"
        : "+f"(c0), "+f"(c1), "+f"(c2), "+f"(c3)
        : "r"(a0), "r"(a1), "r"(a2), "r"(a3), "r"(b0), "r"(b1));
}
static __device__ __forceinline__ void red_v2(float* p, float x, float y) {
    asm volatile("red.global.add.v2.f32 [%0], {%1, %2};"
                 :: "l"(p), "f"(x), "f"(y) : "memory");
}
static __device__ __forceinline__ void mbar_init(uint32_t a, uint32_t n) {
    asm volatile("mbarrier.init.shared.b64 [%0], %1;" :: "r"(a), "r"(n) : "memory");
}
static __device__ __forceinline__ void expect_tx(uint32_t a, uint32_t bytes) {
    asm volatile("mbarrier.arrive.expect_tx.shared.b64 _, [%0], %1;"
                 :: "r"(a), "r"(bytes) : "memory");
}
static __device__ __forceinline__ void mbar_wait(uint32_t a, uint32_t ph) {
    asm volatile("{\n\t.reg .pred P1;\n\t"
        "WL_%=:\n\t"
        "mbarrier.try_wait.parity.acquire.cta.shared::cta.b64 P1, [%0], %1, 0x989680;\n\t"
        "@P1 bra.uni WD_%=;\n\t"
        "bra.uni WL_%=;\n\t"
        "WD_%=:\n\t}" :: "r"(a), "r"(ph) : "memory");
}
static __device__ __forceinline__ void bulk_g2s(uint32_t dst, const void* src,
                                                uint32_t bytes, uint32_t mbar) {
    asm volatile(
        "cp.async.bulk.shared::cta.global.mbarrier::complete_tx::bytes [%0], [%1], %2, [%3];"
        :: "r"(dst), "l"(src), "r"(bytes), "r"(mbar) : "memory");
}
#define FENCE_ASYNC() asm volatile("fence.proxy.async.shared::cta;" ::: "memory")

__global__ void __launch_bounds__(THREADS, 3)
spconv_mma(const float* __restrict__ feats, const float* __restrict__ weight,
           const void* __restrict__ in_map, const void* __restrict__ out_map,
           float* __restrict__ out, int M, int tilesPerK, int nTiles, int chunk)
{
    extern __shared__ __align__(16) char smem[];
    const uint32_t sb = smem_u32(smem);

    const int t0 = blockIdx.x * chunk;
    if (t0 >= nTiles) return;
    const int tEnd = min(t0 + chunk, nTiles);

    const int tid  = threadIdx.x;
    const int wid  = tid >> 5;          // 0..7
    const int lane = tid & 31;
    const int grp  = lane >> 2;
    const int tig  = lane & 3;
    const int wbase = wid * 16;         // each warp owns 16 rows of the 128-row tile
    const int is64  = g_idx_is64;
    const int idxsz = is64 ? 8 : 4;

    if (tid == 0) { mbar_init(sb + OFF_MBAR, 1); mbar_init(sb + OFF_MBAR + 8, 1); }
    __syncthreads();

#define MBAR(s) (sb + OFF_MBAR + 8u * (uint32_t)(s))
#define ROWS_OF(t)   min(M_TILE, M - ((t) % tilesPerK) * M_TILE)
#define MAP_OFF(t)   ((long long)((t) / tilesPerK) * M + ((t) % tilesPerK) * M_TILE)

    int ph[2] = {0, 0};
    const int cur0 = t0 & 1, nxt0 = cur0 ^ 1;
    const int rows0 = ROWS_OF(t0);

    // ---- prologue stage A: fetch in-idx(t0) ----
    if (tid == 0) {
        expect_tx(MBAR(cur0), (uint32_t)(rows0 * idxsz));
        bulk_g2s(sb + OFF_IN(cur0), (const char*)in_map + MAP_OFF(t0) * idxsz,
                 rows0 * idxsz, MBAR(cur0));
    }
    mbar_wait(MBAR(cur0), 0); ph[cur0] = 1;

    // ---- prologue stage B: gather A(t0), out-idx(t0), in-idx(t0+1) ----
    {
        int rows1b = (t0 + 1 < tEnd) ? ROWS_OF(t0 + 1) : 0;
        uint32_t bytes = (uint32_t)(rows0 * 256 + rows0 * idxsz + rows1b * idxsz);
        if (tid == 0) expect_tx(MBAR(nxt0), bytes);
        if (tid < rows0) {
            long long ii = is64 ? ((const long long*)(smem + OFF_IN(cur0)))[tid]
                                : (long long)((const int*)(smem + OFF_IN(cur0)))[tid];
            bulk_g2s(sb + OFF_A(cur0) + tid * A_ROW_BYTES, feats + ii * C_IN, 256, MBAR(nxt0));
        }
        if (tid == 0)
            bulk_g2s(sb + OFF_OUT(cur0), (const char*)out_map + MAP_OFF(t0) * idxsz,
                     rows0 * idxsz, MBAR(nxt0));
        if (tid == 1 && rows1b)
            bulk_g2s(sb + OFF_IN(nxt0), (const char*)in_map + MAP_OFF(t0 + 1) * idxsz,
                     rows1b * idxsz, MBAR(nxt0));
    }

    uint32_t B[8][4][2];
    int k_cur = -1;

    for (int t = t0; t < tEnd; ++t) {
        const int cur = t & 1, nxt = cur ^ 1;

        // wait for everything issued last iteration (A[cur], idx for t+1, out-idx t)
        mbar_wait(MBAR(nxt), ph[nxt]); ph[nxt] ^= 1;
        __syncthreads();

        const int k    = t / tilesPerK;
        const int rows = ROWS_OF(t);

        if (k != k_cur) {   // <=2x per CTA (contiguous chunks)
            k_cur = k;
            const float* Wk = weight + (size_t)k * C_IN * C_OUT;
#pragma unroll
            for (int kt = 0; kt < 8; ++kt)
#pragma unroll
                for (int nt = 0; nt < 4; ++nt) {
                    B[kt][nt][0] = cvt_tf32(Wk[(8 * kt + tig)     * C_OUT + 8 * nt + grp]);
                    B[kt][nt][1] = cvt_tf32(Wk[(8 * kt + tig + 4) * C_OUT + 8 * nt + grp]);
                }
        }

        // ---- issue next tile's async fetches (hidden behind MMA+scatter below) ----
        FENCE_ASYNC();
        const int rows1 = (t + 1 < tEnd) ? ROWS_OF(t + 1) : 0;
        const int rows2 = (t + 2 < tEnd) ? ROWS_OF(t + 2) : 0;
        uint32_t bytes = (uint32_t)(rows1 * (256 + idxsz) + rows2 * idxsz);
        if (bytes && tid == 0) expect_tx(MBAR(cur), bytes);
        if (rows1) {
            if (tid < rows1) {
                long long ii = is64 ? ((const long long*)(smem + OFF_IN(nxt)))[tid]
                                    : (long long)((const int*)(smem + OFF_IN(nxt)))[tid];
                bulk_g2s(sb + OFF_A(nxt) + tid * A_ROW_BYTES, feats + ii * C_IN, 256, MBAR(cur));
            }
            if (tid == 0)
                bulk_g2s(sb + OFF_OUT(nxt), (const char*)out_map + MAP_OFF(t + 1) * idxsz,
                         rows1 * idxsz, MBAR(cur));
        }
        if (rows2 && tid == 1)
            bulk_g2s(sb + OFF_IN(cur), (const char*)in_map + MAP_OFF(t + 2) * idxsz,
                     rows2 * idxsz, MBAR(cur));

        // ---- MMA: 16 rows x 32 cols x 64 k per warp = 32 HMMA ----
        float acc[4][4];
#pragma unroll
        for (int nt = 0; nt < 4; ++nt)
#pragma unroll
            for (int i = 0; i < 4; ++i) acc[nt][i] = 0.f;

        const float* A = (const float*)(smem + OFF_A(cur));
#pragma unroll
        for (int kt = 0; kt < 8; ++kt) {
            const float* Ar = &A[(wbase + grp) * A_STRIDE_F + kt * 8 + tig];
            uint32_t a0 = __float_as_uint(Ar[0]);
            uint32_t a1 = __float_as_uint(Ar[8 * A_STRIDE_F]);
            uint32_t a2 = __float_as_uint(Ar[4]);
            uint32_t a3 = __float_as_uint(Ar[8 * A_STRIDE_F + 4]);
#pragma unroll
            for (int nt = 0; nt < 4; ++nt)
                mma_tf32(acc[nt][0], acc[nt][1], acc[nt][2], acc[nt][3],
                         a0, a1, a2, a3, B[kt][nt][0], B[kt][nt][1]);
        }

        // ---- scatter epilogue: direct red.v2 from C-frags ----
        {
            const char* osm = smem + OFF_OUT(cur);
            int r0 = wbase + grp;
            int r1 = r0 + 8;
            bool v0 = r0 < rows, v1 = r1 < rows;
            uint32_t o0 = 0, o1 = 0;
            if (v0) o0 = is64 ? (uint32_t)((const long long*)osm)[r0]
                              : (uint32_t)((const int*)osm)[r0];
            if (v1) o1 = is64 ? (uint32_t)((const long long*)osm)[r1]
                              : (uint32_t)((const int*)osm)[r1];
            float* p0 = out + o0 * (uint32_t)C_OUT + 2 * tig;
            float* p1 = out + o1 * (uint32_t)C_OUT + 2 * tig;
#pragma unroll
            for (int nt = 0; nt < 4; ++nt) {
                if (v0) red_v2(p0 + 8 * nt, acc[nt][0], acc[nt][1]);
                if (v1) red_v2(p1 + 8 * nt, acc[nt][2], acc[nt][3]);
            }
        }
    }
#undef MBAR
#undef ROWS_OF
#undef MAP_OFF
}

extern "C" void kernel_launch(void* const* d_in, const int* in_sizes, int n_in,
                              void* d_out, int out_size) {
    const float* feats  = (const float*)d_in[0];
    const float* weight = (const float*)d_in[1];
    const void*  in_map  = d_in[2];
    const void*  out_map = d_in[3];

    int K = in_sizes[1] / (C_IN * C_OUT);           // 27
    int M = in_sizes[2] / K;                        // 100000
    int tilesPerK = (M + M_TILE - 1) / M_TILE;      // 782
    int nTiles = K * tilesPerK;                     // 21114
    int chunk = (nTiles + GRID - 1) / GRID;         // 48

    static int attr_done = 0;
    if (!attr_done) {
        cudaFuncSetAttribute(spconv_mma,
                             cudaFuncAttributeMaxDynamicSharedMemorySize, SMEM_TOTAL);
        attr_done = 1;
    }

    cudaMemsetAsync(d_out, 0, (size_t)out_size * sizeof(float));
    detect_idx_kernel<<<1, 1>>>((const long long*)in_map);
    spconv_mma<<<GRID, THREADS, SMEM_TOTAL>>>(feats, weight, in_map, out_map,
                                              (float*)d_out, M, tilesPerK, nTiles, chunk);
}

// round 9
// speedup vs baseline: 1.3732x; 1.3372x over previous
#include <cuda_runtime.h>
#include <cuda_fp16.h>
#include <cstdint>

#define C_IN    64
#define C_OUT   32
#define M_TILE  128
#define THREADS 256
#define GRID    444
#define N_IN_MAX 100000
#define A_STRIDE_B 144      // bytes per A row: 128 fp16 data + 16 pad (ldmatrix conflict-free)
#define A_TILE_B  (M_TILE * A_STRIDE_B)   // 18432

// dynamic smem layout (byte offsets, 16B aligned)
#define OFF_IN(s)   ((s) * 1024)
#define OFF_OUT(s)  (2048 + (s) * 1024)
#define OFF_MBAR    4096
#define OFF_A(s)    (4352 + (s) * A_TILE_B)
#define SMEM_TOTAL  (4352 + 2 * A_TILE_B)   // 41216

__device__ __align__(16) __half g_featsH[N_IN_MAX * C_IN];   // fp16 feats scratch

// Runtime-detected index width (reference's int64 maps may have been silently
// downcast to int32 by JAX when x64 is disabled).
__device__ int g_idx_is64;
__global__ void detect_idx_kernel(const long long* __restrict__ im) {
    int is64 = 1;
#pragma unroll
    for (int t = 0; t < 16; ++t) {
        long long v = im[t];
        if (v < 0 || v >= (1ll << 31)) is64 = 0;
    }
    g_idx_is64 = is64;
}

// fused prep: feats fp32 -> fp16 scratch, and zero d_out
__global__ void prep_kernel(const float2* __restrict__ feats, int n2,
                            float4* __restrict__ out, int n4) {
    int i = blockIdx.x * blockDim.x + threadIdx.x;
    int stride = gridDim.x * blockDim.x;
    __half2* fh = (__half2*)g_featsH;
    for (int j = i; j < n2; j += stride) {
        float2 v = feats[j];
        fh[j] = __floats2half2_rn(v.x, v.y);
    }
    float4 z = make_float4(0.f, 0.f, 0.f, 0.f);
    for (int j = i; j < n4; j += stride) out[j] = z;
}

static __device__ __forceinline__ uint32_t smem_u32(const void* p) {
    uint32_t a;
    asm("{ .reg .u64 t; cvta.to.shared.u64 t, %1; cvt.u32.u64 %0, t; }" : "=r"(a) : "l"(p));
    return a;
}
static __device__ __forceinline__ void ldm_x4(uint32_t& a0, uint32_t& a1,
                                              uint32_t& a2, uint32_t& a3, uint32_t sa) {
    asm volatile("ldmatrix.sync.aligned.m8n8.x4.shared.b16 {%0,%1,%2,%3}, [%4];"
                 : "=r"(a0), "=r"(a1), "=r"(a2), "=r"(a3) : "r"(sa));
}
static __device__ __forceinline__ void mma_f16(
    float& c0, float& c1, float& c2, float& c3,
    uint32_t a0, uint32_t a1, uint32_t a2, uint32_t a3,
    uint32_t b0, uint32_t b1)
{
    asm volatile(
        "mma.sync.aligned.m16n8k16.row.col.f32.f16.f16.f32 "
        "{%0,%1,%2,%3}, {%4,%5,%6,%7}, {%8,%9}, {%0,%1,%2,%3};"
        : "+f"(c0), "+f"(c1), "+f"(c2), "+f"(c3)
        : "r"(a0), "r"(a1), "r"(a2), "r"(a3), "r"(b0), "r"(b1));
}
static __device__ __forceinline__ void red_v2(float* p, float x, float y) {
    asm volatile("red.global.add.v2.f32 [%0], {%1, %2};"
                 :: "l"(p), "f"(x), "f"(y) : "memory");
}
static __device__ __forceinline__ uint32_t h2u(__half2 h) {
    return *(uint32_t*)&h;
}
static __device__ __forceinline__ void mbar_init(uint32_t a, uint32_t n) {
    asm volatile("mbarrier.init.shared.b64 [%0], %1;" :: "r"(a), "r"(n) : "memory");
}
static __device__ __forceinline__ void expect_tx(uint32_t a, uint32_t bytes) {
    asm volatile("mbarrier.arrive.expect_tx.shared.b64 _, [%0], %1;"
                 :: "r"(a), "r"(bytes) : "memory");
}
static __device__ __forceinline__ void mbar_wait(uint32_t a, uint32_t ph) {
    asm volatile("{\n\t.reg .pred P1;\n\t"
        "WL_%=:\n\t"
        "mbarrier.try_wait.parity.acquire.cta.shared::cta.b64 P1, [%0], %1, 0x989680;\n\t"
        "@P1 bra.uni WD_%=;\n\t"
        "bra.uni WL_%=;\n\t"
        "WD_%=:\n\t}" :: "r"(a), "r"(ph) : "memory");
}
static __device__ __forceinline__ void bulk_g2s(uint32_t dst, const void* src,
                                                uint32_t bytes, uint32_t mbar) {
    asm volatile(
        "cp.async.bulk.shared::cta.global.mbarrier::complete_tx::bytes [%0], [%1], %2, [%3];"
        :: "r"(dst), "l"(src), "r"(bytes), "r"(mbar) : "memory");
}
#define FENCE_ASYNC() asm volatile("fence.proxy.async.shared::cta;" ::: "memory")

__global__ void __launch_bounds__(THREADS, 3)
spconv_mma(const float* __restrict__ weight,
           const void* __restrict__ in_map, const void* __restrict__ out_map,
           float* __restrict__ out, int M, int tilesPerK, int nTiles, int chunk)
{
    extern __shared__ __align__(16) char smem[];
    const uint32_t sb = smem_u32(smem);

    const int t0 = blockIdx.x * chunk;
    if (t0 >= nTiles) return;
    const int tEnd = min(t0 + chunk, nTiles);

    const int tid  = threadIdx.x;
    const int wid  = tid >> 5;          // 0..7
    const int lane = tid & 31;
    const int grp  = lane >> 2;
    const int tig  = lane & 3;
    const int wbase = wid * 16;         // each warp owns 16 rows of the tile
    const int is64  = g_idx_is64;
    const int idxsz = is64 ? 8 : 4;

    // ldmatrix per-lane source offset within the A tile (fixed per thread)
    const int lr = lane & 7, sel = lane >> 3;
    const uint32_t a_lane_off =
        (uint32_t)((wbase + lr + ((sel & 1) << 3)) * A_STRIDE_B + ((sel >> 1) << 4));

    if (tid == 0) { mbar_init(sb + OFF_MBAR, 1); mbar_init(sb + OFF_MBAR + 8, 1); }
    __syncthreads();

#define MBAR(s) (sb + OFF_MBAR + 8u * (uint32_t)(s))
#define ROWS_OF(t)   min(M_TILE, M - ((t) % tilesPerK) * M_TILE)
#define MAP_OFF(t)   ((long long)((t) / tilesPerK) * M + ((t) % tilesPerK) * M_TILE)

    int ph[2] = {0, 0};
    const int cur0 = t0 & 1, nxt0 = cur0 ^ 1;
    const int rows0 = ROWS_OF(t0);

    // ---- prologue stage A: fetch in-idx(t0) ----
    if (tid == 0) {
        expect_tx(MBAR(cur0), (uint32_t)(rows0 * idxsz));
        bulk_g2s(sb + OFF_IN(cur0), (const char*)in_map + MAP_OFF(t0) * idxsz,
                 rows0 * idxsz, MBAR(cur0));
    }
    mbar_wait(MBAR(cur0), 0); ph[cur0] = 1;

    // ---- prologue stage B: gather A(t0) fp16 rows, out-idx(t0), in-idx(t0+1) ----
    {
        int rows1b = (t0 + 1 < tEnd) ? ROWS_OF(t0 + 1) : 0;
        uint32_t bytes = (uint32_t)(rows0 * 128 + rows0 * idxsz + rows1b * idxsz);
        if (tid == 0) expect_tx(MBAR(nxt0), bytes);
        if (tid < rows0) {
            long long ii = is64 ? ((const long long*)(smem + OFF_IN(cur0)))[tid]
                                : (long long)((const int*)(smem + OFF_IN(cur0)))[tid];
            bulk_g2s(sb + OFF_A(cur0) + tid * A_STRIDE_B, g_featsH + ii * C_IN, 128, MBAR(nxt0));
        }
        if (tid == 0)
            bulk_g2s(sb + OFF_OUT(cur0), (const char*)out_map + MAP_OFF(t0) * idxsz,
                     rows0 * idxsz, MBAR(nxt0));
        if (tid == 1 && rows1b)
            bulk_g2s(sb + OFF_IN(nxt0), (const char*)in_map + MAP_OFF(t0 + 1) * idxsz,
                     rows1b * idxsz, MBAR(nxt0));
    }

    uint32_t B[4][4][2];   // [k-chunk16][n-tile8][2], fp16x2
    int k_cur = -1;

    for (int t = t0; t < tEnd; ++t) {
        const int cur = t & 1, nxt = cur ^ 1;

        mbar_wait(MBAR(nxt), ph[nxt]); ph[nxt] ^= 1;
        __syncthreads();

        const int k    = t / tilesPerK;
        const int rows = ROWS_OF(t);

        if (k != k_cur) {   // <=2x per CTA (contiguous chunks)
            k_cur = k;
            const float* Wk = weight + (size_t)k * C_IN * C_OUT;
#pragma unroll
            for (int kc = 0; kc < 4; ++kc)
#pragma unroll
                for (int nt = 0; nt < 4; ++nt) {
                    const float* Wc = Wk + (kc * 16) * C_OUT + 8 * nt + grp;
                    B[kc][nt][0] = h2u(__floats2half2_rn(Wc[(2 * tig)     * C_OUT],
                                                         Wc[(2 * tig + 1) * C_OUT]));
                    B[kc][nt][1] = h2u(__floats2half2_rn(Wc[(2 * tig + 8) * C_OUT],
                                                         Wc[(2 * tig + 9) * C_OUT]));
                }
        }

        // ---- issue next tile's async fetches (hidden behind MMA+scatter) ----
        FENCE_ASYNC();
        const int rows1 = (t + 1 < tEnd) ? ROWS_OF(t + 1) : 0;
        const int rows2 = (t + 2 < tEnd) ? ROWS_OF(t + 2) : 0;
        uint32_t bytes = (uint32_t)(rows1 * (128 + idxsz) + rows2 * idxsz);
        if (bytes && tid == 0) expect_tx(MBAR(cur), bytes);
        if (rows1) {
            if (tid < rows1) {
                long long ii = is64 ? ((const long long*)(smem + OFF_IN(nxt)))[tid]
                                    : (long long)((const int*)(smem + OFF_IN(nxt)))[tid];
                bulk_g2s(sb + OFF_A(nxt) + tid * A_STRIDE_B, g_featsH + ii * C_IN, 128, MBAR(cur));
            }
            if (tid == 0)
                bulk_g2s(sb + OFF_OUT(nxt), (const char*)out_map + MAP_OFF(t + 1) * idxsz,
                         rows1 * idxsz, MBAR(cur));
        }
        if (rows2 && tid == 1)
            bulk_g2s(sb + OFF_IN(cur), (const char*)in_map + MAP_OFF(t + 2) * idxsz,
                     rows2 * idxsz, MBAR(cur));

        // ---- MMA: 16 rows x 32 cols x 64 k per warp = 4 ldmatrix.x4 + 16 HMMA ----
        float acc[4][4];
#pragma unroll
        for (int nt = 0; nt < 4; ++nt)
#pragma unroll
            for (int i = 0; i < 4; ++i) acc[nt][i] = 0.f;

        const uint32_t abase = sb + OFF_A(cur) + a_lane_off;
#pragma unroll
        for (int kc = 0; kc < 4; ++kc) {
            uint32_t a0, a1, a2, a3;
            ldm_x4(a0, a1, a2, a3, abase + kc * 32);
#pragma unroll
            for (int nt = 0; nt < 4; ++nt)
                mma_f16(acc[nt][0], acc[nt][1], acc[nt][2], acc[nt][3],
                        a0, a1, a2, a3, B[kc][nt][0], B[kc][nt][1]);
        }

        // ---- scatter epilogue: direct red.v2 from C-frags ----
        {
            const char* osm = smem + OFF_OUT(cur);
            int r0 = wbase + grp;
            int r1 = r0 + 8;
            bool v0 = r0 < rows, v1 = r1 < rows;
            uint32_t o0 = 0, o1 = 0;
            if (v0) o0 = is64 ? (uint32_t)((const long long*)osm)[r0]
                              : (uint32_t)((const int*)osm)[r0];
            if (v1) o1 = is64 ? (uint32_t)((const long long*)osm)[r1]
                              : (uint32_t)((const int*)osm)[r1];
            float* p0 = out + o0 * (uint32_t)C_OUT + 2 * tig;
            float* p1 = out + o1 * (uint32_t)C_OUT + 2 * tig;
#pragma unroll
            for (int nt = 0; nt < 4; ++nt) {
                if (v0) red_v2(p0 + 8 * nt, acc[nt][0], acc[nt][1]);
                if (v1) red_v2(p1 + 8 * nt, acc[nt][2], acc[nt][3]);
            }
        }
    }
#undef MBAR
#undef ROWS_OF
#undef MAP_OFF
}

extern "C" void kernel_launch(void* const* d_in, const int* in_sizes, int n_in,
                              void* d_out, int out_size) {
    const float* feats  = (const float*)d_in[0];
    const float* weight = (const float*)d_in[1];
    const void*  in_map  = d_in[2];
    const void*  out_map = d_in[3];

    int K = in_sizes[1] / (C_IN * C_OUT);           // 27
    int M = in_sizes[2] / K;                        // 100000
    int tilesPerK = (M + M_TILE - 1) / M_TILE;      // 782
    int nTiles = K * tilesPerK;                     // 21114
    int chunk = (nTiles + GRID - 1) / GRID;         // 48

    static int attr_done = 0;
    if (!attr_done) {
        cudaFuncSetAttribute(spconv_mma,
                             cudaFuncAttributeMaxDynamicSharedMemorySize, SMEM_TOTAL);
        attr_done = 1;
    }

    prep_kernel<<<592, 256>>>((const float2*)feats, in_sizes[0] / 2,
                              (float4*)d_out, out_size / 4);
    detect_idx_kernel<<<1, 1>>>((const long long*)in_map);
    spconv_mma<<<GRID, THREADS, SMEM_TOTAL>>>(weight, in_map, out_map,
                                              (float*)d_out, M, tilesPerK, nTiles, chunk);
}